// round 14
// baseline (speedup 1.0000x reference)
#include <cuda_runtime.h>
#include <math.h>

// L=2, H=1024, HM=256, E=64, B=64, T=256, D=1024
// rows = B*T = 16384, 4H = 4096, 4HM = 1024, D+H = 2048, recur K = 1280

// ---------------- scratch (__device__ globals, allowed) ----------------
__device__ float g_Gx[16384L * 4096];     // gx precompute [b*T+t][4096]
__device__ float g_Mx[16384L * 1024];     // x-part of mpre (+bm) [b*T+t][1024]
__device__ float g_X1[16384L * 1024];     // layer-0 output
__device__ float g_Wpack[1024L * 1280];   // packed [Wmx_h | Wmh] as [n][1280]
__device__ float g_Acat[64 * 1280];       // per-batch [h(1024) | mh(256)]
__device__ float g_c[64 * 1024];          // main cell
__device__ float g_mc[64 * 256];          // meta cell
__device__ float g_mpart[8L * 64 * 1024]; // meta GEMM K-split partials
__device__ float g_gpart[2L * 64 * 4096]; // main GEMM K-split partials
__device__ float g_z[3L * 64 * 256];      // z [s][b][g*64+e]
__device__ float g_d[3L * 64 * 4096];     // d [s][b][g*1024+h]

__device__ unsigned g_cnt = 0;
__device__ volatile unsigned g_gen = 0;

__device__ __forceinline__ float sigf(float x) { return 1.0f / (1.0f + expf(-x)); }

// sense-reversing grid barrier (all blocks of the one-wave grid participate)
__device__ __forceinline__ void gridbar(unsigned nb, unsigned& sense)
{
    __syncthreads();
    if (threadIdx.x == 0) {
        __threadfence();
        unsigned a = atomicAdd(&g_cnt, 1u);
        if (a == nb - 1u) {
            g_cnt = 0;
            __threadfence();
            g_gen = sense + 1u;
        } else {
            while (g_gen != sense + 1u) { __nanosleep(32); }
        }
        __threadfence();
    }
    sense += 1u;
    __syncthreads();
}

// ---------------- big precompute SGEMM: C[16384,N] = A[16384,1024] @ W[N,ldw]^T (+bias) ----
__global__ __launch_bounds__(256) void sgemm128(
    const float* __restrict__ A, const float* __restrict__ W, int ldw,
    const float* __restrict__ bias, float* __restrict__ C, int N)
{
    __shared__ float As[8][132];
    __shared__ float Ws[8][132];
    int tid  = threadIdx.x;
    int m0   = blockIdx.y * 128;
    int n0   = blockIdx.x * 128;
    int lrow = tid >> 1;
    int lk4  = (tid & 1) * 4;
    const float* Aload = A + (long)(m0 + lrow) * 1024 + lk4;
    const float* Wload = W + (long)(n0 + lrow) * ldw + lk4;
    int tr = (tid >> 4) * 8;
    int tc = (tid & 15) * 8;

    float acc[8][8];
#pragma unroll
    for (int i = 0; i < 8; i++)
#pragma unroll
        for (int j = 0; j < 8; j++) acc[i][j] = 0.0f;

    for (int k0 = 0; k0 < 1024; k0 += 8) {
        float4 av = *(const float4*)(Aload + k0);
        float4 wv = *(const float4*)(Wload + k0);
        As[lk4 + 0][lrow] = av.x; As[lk4 + 1][lrow] = av.y;
        As[lk4 + 2][lrow] = av.z; As[lk4 + 3][lrow] = av.w;
        Ws[lk4 + 0][lrow] = wv.x; Ws[lk4 + 1][lrow] = wv.y;
        Ws[lk4 + 2][lrow] = wv.z; Ws[lk4 + 3][lrow] = wv.w;
        __syncthreads();
#pragma unroll
        for (int k = 0; k < 8; k++) {
            float4 a0 = *(const float4*)&As[k][tr];
            float4 a1 = *(const float4*)&As[k][tr + 4];
            float4 w0 = *(const float4*)&Ws[k][tc];
            float4 w1 = *(const float4*)&Ws[k][tc + 4];
            float a[8] = {a0.x, a0.y, a0.z, a0.w, a1.x, a1.y, a1.z, a1.w};
            float w[8] = {w0.x, w0.y, w0.z, w0.w, w1.x, w1.y, w1.z, w1.w};
#pragma unroll
            for (int i = 0; i < 8; i++)
#pragma unroll
                for (int j = 0; j < 8; j++) acc[i][j] += a[i] * w[j];
        }
        __syncthreads();
    }
#pragma unroll
    for (int i = 0; i < 8; i++) {
        float* cp = C + (long)(m0 + tr + i) * N + n0 + tc;
#pragma unroll
        for (int j = 0; j < 8; j++) {
            float v = acc[i][j];
            if (bias) v += bias[n0 + tc + j];
            cp[j] = v;
        }
    }
}

// ---------------- pack [Wmx_h | Wmh] into k-contiguous [n][1280] ----------
__global__ void pack_meta(const float* __restrict__ Wmx_l, const float* __restrict__ Wmh_l)
{
    int idx = blockIdx.x * 256 + threadIdx.x;
    if (idx >= 1024 * 1280) return;
    int n = idx / 1280;
    int k = idx - n * 1280;
    g_Wpack[idx] = (k < 1024) ? Wmx_l[n * 2048 + 1024 + k]
                              : Wmh_l[n * 256 + (k - 1024)];
}

// ---------------- device helpers for the persistent recurrence kernel -----------

// 64b x 64n tile of Cp[kyIdx][64,N] = Acat[64, ky..ky+Ksub) @ W[N,ldw]^T
__device__ __forceinline__ void skinny_tile(
    const float* __restrict__ W, int ldw,
    float* __restrict__ Cp, int N, int Ksub, int n0, int kyIdx, float* sm)
{
    float* As = sm;            // 32*72
    float* Ws = sm + 32 * 72;  // 32*72
    int tid  = threadIdx.x;
    int ky   = kyIdx * Ksub;
    int lrow = tid >> 2;
    int lk   = (tid & 3) * 8;
    const float* Aload = g_Acat + lrow * 1280 + ky + lk;
    const float* Wload = W + (long)(n0 + lrow) * ldw + ky + lk;
    int tb = (tid >> 4) * 4;
    int tc = (tid & 15) * 4;

    float acc[4][4];
#pragma unroll
    for (int i = 0; i < 4; i++)
#pragma unroll
        for (int j = 0; j < 4; j++) acc[i][j] = 0.0f;

    for (int k0 = 0; k0 < Ksub; k0 += 32) {
        float4 a0 = *(const float4*)(Aload + k0);
        float4 a1 = *(const float4*)(Aload + k0 + 4);
        float4 w0 = *(const float4*)(Wload + k0);
        float4 w1 = *(const float4*)(Wload + k0 + 4);
        As[(lk + 0) * 72 + lrow] = a0.x; As[(lk + 1) * 72 + lrow] = a0.y;
        As[(lk + 2) * 72 + lrow] = a0.z; As[(lk + 3) * 72 + lrow] = a0.w;
        As[(lk + 4) * 72 + lrow] = a1.x; As[(lk + 5) * 72 + lrow] = a1.y;
        As[(lk + 6) * 72 + lrow] = a1.z; As[(lk + 7) * 72 + lrow] = a1.w;
        Ws[(lk + 0) * 72 + lrow] = w0.x; Ws[(lk + 1) * 72 + lrow] = w0.y;
        Ws[(lk + 2) * 72 + lrow] = w0.z; Ws[(lk + 3) * 72 + lrow] = w0.w;
        Ws[(lk + 4) * 72 + lrow] = w1.x; Ws[(lk + 5) * 72 + lrow] = w1.y;
        Ws[(lk + 6) * 72 + lrow] = w1.z; Ws[(lk + 7) * 72 + lrow] = w1.w;
        __syncthreads();
#pragma unroll
        for (int k = 0; k < 32; k++) {
            float4 av = *(const float4*)&As[k * 72 + tb];
            float4 wv = *(const float4*)&Ws[k * 72 + tc];
            float a[4] = {av.x, av.y, av.z, av.w};
            float w[4] = {wv.x, wv.y, wv.z, wv.w};
#pragma unroll
            for (int i = 0; i < 4; i++)
#pragma unroll
                for (int j = 0; j < 4; j++) acc[i][j] += a[i] * w[j];
        }
        __syncthreads();
    }
#pragma unroll
    for (int i = 0; i < 4; i++) {
        float4 v = make_float4(acc[i][0], acc[i][1], acc[i][2], acc[i][3]);
        *(float4*)(Cp + ((long)kyIdx * 64 + tb + i) * N + n0 + tc) = v;
    }
}

// meta cell update + z projections for batch b (one block)
__device__ __forceinline__ void meta_dev(
    int t, int b,
    const float* __restrict__ Wzx_l, const float* __restrict__ Wzh_l,
    const float* __restrict__ Wzb_l,
    const float* __restrict__ bzx_l, const float* __restrict__ bzh_l, float* smem)
{
    float* sm  = smem;          // 1024
    float* smh = smem + 1024;   // 256
    int tid = threadIdx.x;
    const float* mx = g_Mx + ((long)b * 256 + t) * 1024;
#pragma unroll
    for (int jj = 0; jj < 4; jj++) {
        int j = tid + jj * 256;
        float v = mx[j];
#pragma unroll
        for (int ks = 0; ks < 8; ks++) v += g_mpart[(ks * 64 + b) * 1024 + j];
        sm[j] = v;
    }
    __syncthreads();
    {
        int j = tid;
        float mi = sm[j], mf = sm[256 + j], mg = sm[512 + j], mo = sm[768 + j];
        float mco = g_mc[b * 256 + j];
        float mc2 = sigf(mf) * mco + sigf(mi) * tanhf(mg);
        float mh2 = sigf(mo) * tanhf(mc2);
        g_mc[b * 256 + j] = mc2;
        g_Acat[b * 1280 + 1024 + j] = mh2;
        smh[j] = mh2;
    }
    __syncthreads();
    if (tid < 128) {
        int g  = tid >> 5;
        int e0 = (tid & 31) * 2;
        float2 ax = *(const float2*)&bzx_l[g * 64 + e0];
        float2 ah = *(const float2*)&bzh_l[g * 64 + e0];
        float2 ab = make_float2(0.0f, 0.0f);
        const float* wx = Wzx_l + g * 64 + e0;   // stride per m: 256
        const float* wh = Wzh_l + g * 64 + e0;
        const float* wb = Wzb_l + g * 64 + e0;
#pragma unroll 4
        for (int m = 0; m < 256; m++) {
            float mv = smh[m];
            float2 vx = *(const float2*)(wx + m * 256);
            float2 vh = *(const float2*)(wh + m * 256);
            float2 vb = *(const float2*)(wb + m * 256);
            ax.x += mv * vx.x; ax.y += mv * vx.y;
            ah.x += mv * vh.x; ah.y += mv * vh.y;
            ab.x += mv * vb.x; ab.y += mv * vb.y;
        }
        int zo = b * 256 + g * 64 + e0;
        *(float2*)&g_z[0 * 64 * 256 + zo] = ax;
        *(float2*)&g_z[1 * 64 * 256 + zo] = ah;
        *(float2*)&g_z[2 * 64 * 256 + zo] = ab;
    }
    __syncthreads();
}

// d[s][b][g*1024+h] = sum_e z[s][b][g,e] * P_s[g][e][h]; 64b x 64hh tile
__device__ __forceinline__ void dcoef_dev(
    int hhTile, int g, int s,
    const float* __restrict__ Px_l, const float* __restrict__ Ph_l,
    const float* __restrict__ Pb_l, float* smem)
{
    float* zs = smem;             // 64*68
    float* ps = smem + 64 * 68;   // 64*68
    int tid = threadIdx.x;
    int hh0 = hhTile * 64;
    const float* P = (s == 0) ? Px_l : ((s == 1) ? Ph_l : Pb_l);
    {   // z -> zs[e][b]
        int lb  = tid >> 2;
        int le0 = (tid & 3) * 16;
        const float* zp = g_z + (s * 64 + lb) * 256 + g * 64 + le0;
#pragma unroll
        for (int q = 0; q < 4; q++) {
            float4 v = *(const float4*)(zp + q * 4);
            zs[(le0 + q * 4 + 0) * 68 + lb] = v.x;
            zs[(le0 + q * 4 + 1) * 68 + lb] = v.y;
            zs[(le0 + q * 4 + 2) * 68 + lb] = v.z;
            zs[(le0 + q * 4 + 3) * 68 + lb] = v.w;
        }
    }
    {   // P -> ps[e][hh]
        int le = tid >> 2;
        int j0 = (tid & 3) * 16;
        const float* pp = P + ((long)g * 64 + le) * 1024 + hh0 + j0;
#pragma unroll
        for (int q = 0; q < 4; q++)
            *(float4*)&ps[le * 68 + j0 + q * 4] = *(const float4*)(pp + q * 4);
    }
    __syncthreads();
    int tb = (tid >> 4) * 4;
    int th = (tid & 15) * 4;
    float acc[4][4];
#pragma unroll
    for (int i = 0; i < 4; i++)
#pragma unroll
        for (int j = 0; j < 4; j++) acc[i][j] = 0.0f;
#pragma unroll 8
    for (int e = 0; e < 64; e++) {
        float4 zv = *(const float4*)&zs[e * 68 + tb];
        float4 pv = *(const float4*)&ps[e * 68 + th];
        float a[4] = {zv.x, zv.y, zv.z, zv.w};
        float w[4] = {pv.x, pv.y, pv.z, pv.w};
#pragma unroll
        for (int i = 0; i < 4; i++)
#pragma unroll
            for (int j = 0; j < 4; j++) acc[i][j] += a[i] * w[j];
    }
#pragma unroll
    for (int i = 0; i < 4; i++) {
        float4 v = make_float4(acc[i][0], acc[i][1], acc[i][2], acc[i][3]);
        *(float4*)&g_d[((long)s * 64 + tb + i) * 4096 + g * 1024 + hh0 + th] = v;
    }
    __syncthreads();
}

// combine partials, hyper-modulate, LSTM cell update (256 threads per chunk w)
__device__ __forceinline__ void combine_dev(int t, int w, float* __restrict__ Xout)
{
    int idx = w * 256 + threadIdx.x;      // 0..65535 = 64b x 1024h
    int b  = idx >> 10;
    int hh = idx & 1023;
    long rbase = (long)b * 4096 + hh;
    float pre[4];
#pragma unroll
    for (int g = 0; g < 4; g++) {
        long n = rbase + g * 1024;
        float gh = g_gpart[n] + g_gpart[262144 + n];
        float gx = g_Gx[((long)b * 256 + t) * 4096 + g * 1024 + hh];
        pre[g] = g_d[n] * gx + g_d[262144 + n] * gh + g_d[524288 + n];
    }
    float co = g_c[idx];
    float c2 = sigf(pre[1]) * co + sigf(pre[0]) * tanhf(pre[2]);
    float h2 = sigf(pre[3]) * tanhf(c2);
    g_c[idx] = c2;
    g_Acat[b * 1280 + hh] = h2;
    Xout[((long)b * 256 + t) * 1024 + hh] = h2;
}

// ---------------- persistent recurrence: one wave of 148 blocks ----------------
__global__ __launch_bounds__(256, 2) void recur_kernel(
    const float* __restrict__ Wh_l,
    const float* __restrict__ Wzx_l, const float* __restrict__ Wzh_l,
    const float* __restrict__ Wzb_l,
    const float* __restrict__ bzx_l, const float* __restrict__ bzh_l,
    const float* __restrict__ Px_l, const float* __restrict__ Ph_l,
    const float* __restrict__ Pb_l,
    float* __restrict__ Xout)
{
    __shared__ __align__(16) float smem[8704];   // max of all phase needs (34.8 KB)
    unsigned nb  = gridDim.x;
    unsigned bid = blockIdx.x;
    int tid = threadIdx.x;
    unsigned sense = g_gen;   // stable across the grid at kernel entry

    // zero state
    for (int i = bid * 256 + tid; i < 64 * 1280; i += nb * 256) g_Acat[i] = 0.0f;
    for (int i = bid * 256 + tid; i < 64 * 1024; i += nb * 256) g_c[i] = 0.0f;
    for (int i = bid * 256 + tid; i < 64 * 256;  i += nb * 256) g_mc[i] = 0.0f;
    gridbar(nb, sense);

    for (int t = 0; t < 256; t++) {
        // Phase A: meta recurrent GEMM (128 tiles) + main h@Wh^T GEMM (128 tiles)
        for (int w = bid; w < 256; w += nb) {
            if (w < 128) {
                skinny_tile(g_Wpack, 1280, g_mpart, 1024, 160, (w & 15) * 64, w >> 4, smem);
            } else {
                int q = w - 128;
                skinny_tile(Wh_l, 1024, g_gpart, 4096, 512, (q & 63) * 64, q >> 6, smem);
            }
        }
        gridbar(nb, sense);

        // Phase B: meta cell + z projections (64 blocks' worth)
        for (int w = bid; w < 64; w += nb)
            meta_dev(t, w, Wzx_l, Wzh_l, Wzb_l, bzx_l, bzh_l, smem);
        gridbar(nb, sense);

        // Phase C: d = z @ P (192 tiles)
        for (int w = bid; w < 192; w += nb)
            dcoef_dev(w & 15, (w >> 4) & 3, w >> 6, Px_l, Ph_l, Pb_l, smem);
        gridbar(nb, sense);

        // Phase D: combine + LSTM cell update (256 chunks)
        for (int w = bid; w < 256; w += nb)
            combine_dev(t, w, Xout);
        gridbar(nb, sense);
    }
}

// ---------------- host ----------------
extern "C" void kernel_launch(void* const* d_in, const int* in_sizes, int n_in,
                              void* d_out, int out_size)
{
    const float* x   = (const float*)d_in[0];
    const float* Wx  = (const float*)d_in[1];
    const float* Wh  = (const float*)d_in[2];
    const float* Wmx = (const float*)d_in[3];
    const float* Wmh = (const float*)d_in[4];
    const float* bm  = (const float*)d_in[5];
    const float* Wzx = (const float*)d_in[6];
    const float* bzx = (const float*)d_in[7];
    const float* Wzh = (const float*)d_in[8];
    const float* bzh = (const float*)d_in[9];
    const float* Wzb = (const float*)d_in[10];
    const float* Px  = (const float*)d_in[11];
    const float* Ph  = (const float*)d_in[12];
    const float* Pb  = (const float*)d_in[13];

    float *pGx, *pMx, *pX1;
    cudaGetSymbolAddress((void**)&pGx, g_Gx);
    cudaGetSymbolAddress((void**)&pMx, g_Mx);
    cudaGetSymbolAddress((void**)&pX1, g_X1);

    for (int l = 0; l < 2; l++) {
        const float* Xin  = l ? (const float*)pX1 : x;
        float*       Xout = l ? (float*)d_out : pX1;
        const float* Wmx_l = Wmx + (long)l * 1024 * 2048;
        const float* Wmh_l = Wmh + (long)l * 1024 * 256;
        const float* Wh_l  = Wh  + (long)l * 4096 * 1024;
        const float* Wx_l  = Wx  + (long)l * 4096 * 1024;
        const float* Wzx_l = Wzx + (long)l * 65536;
        const float* Wzh_l = Wzh + (long)l * 65536;
        const float* Wzb_l = Wzb + (long)l * 65536;
        const float* bzx_l = bzx + l * 256;
        const float* bzh_l = bzh + l * 256;
        const float* Px_l  = Px + (long)l * 4 * 64 * 1024;
        const float* Ph_l  = Ph + (long)l * 4 * 64 * 1024;
        const float* Pb_l  = Pb + (long)l * 4 * 64 * 1024;

        pack_meta<<<5120, 256>>>(Wmx_l, Wmh_l);
        sgemm128<<<dim3(32, 128), 256>>>(Xin, Wx_l, 1024, nullptr, pGx, 4096);
        sgemm128<<<dim3(8, 128), 256>>>(Xin, Wmx_l, 2048, bm + l * 1024, pMx, 1024);
        recur_kernel<<<148, 256>>>(Wh_l, Wzx_l, Wzh_l, Wzb_l, bzx_l, bzh_l,
                                   Px_l, Ph_l, Pb_l, Xout);
    }
}

// round 15
// speedup vs baseline: 1.0902x; 1.0902x over previous
#include <cuda_runtime.h>
#include <math.h>

// L=2, H=1024, HM=256, E=64, B=64, T=256, D=1024
// rows = B*T = 16384, 4H = 4096, 4HM = 1024, D+H = 2048, recur main K=1024, meta K=1280

// ---------------- scratch (__device__ globals, allowed) ----------------
__device__ float g_Gx[16384L * 4096];      // gx precompute [b*T+t][4096]
__device__ float g_Mx[16384L * 1024];      // x-part of mpre (+bm) [b*T+t][1024]
__device__ float g_X1[16384L * 1024];      // layer-0 output
__device__ float g_Wpack[1024L * 1280];    // packed [Wmx_h | Wmh] as [n][1280]
__device__ float g_Acat[64 * 1280];        // per-batch [h(1024) | mh(256)]
__device__ float g_c[64 * 1024];           // main cell
__device__ float g_mc[64 * 256];           // meta cell
__device__ float g_mpart[16L * 64 * 1024]; // meta GEMM K-split partials (16 splits)
__device__ float g_gpart[8L * 64 * 4096];  // main GEMM K-split partials (8 splits)
__device__ float g_z[3L * 64 * 256];       // z [s][b][g*64+e]
__device__ float g_d[3L * 64 * 4096];      // d [s][b][g*1024+h]

__device__ unsigned g_cnt = 0;
__device__ volatile unsigned g_gen = 0;

__device__ __forceinline__ float sigf(float x) { return 1.0f / (1.0f + expf(-x)); }

// sense-reversing grid barrier (all blocks of the one-wave grid participate)
__device__ __forceinline__ void gridbar(unsigned nb, unsigned& sense)
{
    __syncthreads();
    if (threadIdx.x == 0) {
        __threadfence();
        unsigned a = atomicAdd(&g_cnt, 1u);
        if (a == nb - 1u) {
            g_cnt = 0;
            __threadfence();
            g_gen = sense + 1u;
        } else {
            while (g_gen != sense + 1u) { __nanosleep(32); }
        }
        __threadfence();
    }
    sense += 1u;
    __syncthreads();
}

// ---------------- big precompute SGEMM: C[16384,N] = A[16384,1024] @ W[N,ldw]^T (+bias) ----
// 128x128 tile, 8x8 per thread, double-buffered smem
__global__ __launch_bounds__(256, 2) void sgemm128(
    const float* __restrict__ A, const float* __restrict__ W, int ldw,
    const float* __restrict__ bias, float* __restrict__ C, int N)
{
    __shared__ float As[2][8][132];
    __shared__ float Ws[2][8][132];
    int tid  = threadIdx.x;
    int m0   = blockIdx.y * 128;
    int n0   = blockIdx.x * 128;
    int lrow = tid >> 1;
    int lk4  = (tid & 1) * 4;
    const float* Aload = A + (long)(m0 + lrow) * 1024 + lk4;
    const float* Wload = W + (long)(n0 + lrow) * ldw + lk4;
    int tr = (tid >> 4) * 8;
    int tc = (tid & 15) * 8;

    float acc[8][8];
#pragma unroll
    for (int i = 0; i < 8; i++)
#pragma unroll
        for (int j = 0; j < 8; j++) acc[i][j] = 0.0f;

    float4 ra = *(const float4*)(Aload);
    float4 rw = *(const float4*)(Wload);
    As[0][lk4 + 0][lrow] = ra.x; As[0][lk4 + 1][lrow] = ra.y;
    As[0][lk4 + 2][lrow] = ra.z; As[0][lk4 + 3][lrow] = ra.w;
    Ws[0][lk4 + 0][lrow] = rw.x; Ws[0][lk4 + 1][lrow] = rw.y;
    Ws[0][lk4 + 2][lrow] = rw.z; Ws[0][lk4 + 3][lrow] = rw.w;
    __syncthreads();

    for (int c = 0; c < 128; c++) {               // 1024 / 8 chunks
        if (c < 127) {
            ra = *(const float4*)(Aload + (c + 1) * 8);
            rw = *(const float4*)(Wload + (c + 1) * 8);
        }
        int buf = c & 1;
#pragma unroll
        for (int k = 0; k < 8; k++) {
            float4 a0 = *(const float4*)&As[buf][k][tr];
            float4 a1 = *(const float4*)&As[buf][k][tr + 4];
            float4 w0 = *(const float4*)&Ws[buf][k][tc];
            float4 w1 = *(const float4*)&Ws[buf][k][tc + 4];
            float a[8] = {a0.x, a0.y, a0.z, a0.w, a1.x, a1.y, a1.z, a1.w};
            float w[8] = {w0.x, w0.y, w0.z, w0.w, w1.x, w1.y, w1.z, w1.w};
#pragma unroll
            for (int i = 0; i < 8; i++)
#pragma unroll
                for (int j = 0; j < 8; j++) acc[i][j] += a[i] * w[j];
        }
        if (c < 127) {
            int nb2 = buf ^ 1;
            As[nb2][lk4 + 0][lrow] = ra.x; As[nb2][lk4 + 1][lrow] = ra.y;
            As[nb2][lk4 + 2][lrow] = ra.z; As[nb2][lk4 + 3][lrow] = ra.w;
            Ws[nb2][lk4 + 0][lrow] = rw.x; Ws[nb2][lk4 + 1][lrow] = rw.y;
            Ws[nb2][lk4 + 2][lrow] = rw.z; Ws[nb2][lk4 + 3][lrow] = rw.w;
        }
        __syncthreads();
    }
#pragma unroll
    for (int i = 0; i < 8; i++) {
        float* cp = C + (long)(m0 + tr + i) * N + n0 + tc;
#pragma unroll
        for (int j = 0; j < 8; j++) {
            float v = acc[i][j];
            if (bias) v += bias[n0 + tc + j];
            cp[j] = v;
        }
    }
}

// ---------------- pack [Wmx_h | Wmh] into k-contiguous [n][1280] ----------
__global__ void pack_meta(const float* __restrict__ Wmx_l, const float* __restrict__ Wmh_l)
{
    int idx = blockIdx.x * 256 + threadIdx.x;
    if (idx >= 1024 * 1280) return;
    int n = idx / 1280;
    int k = idx - n * 1280;
    g_Wpack[idx] = (k < 1024) ? Wmx_l[n * 2048 + 1024 + k]
                              : Wmh_l[n * 256 + (k - 1024)];
}

// ---------------- device helpers for persistent recurrence (512 threads) -----------

// 64b x 128n tile of Cp[kyIdx][64,N] = Acat[64, ky..ky+Ksub) @ W[N,ldw]^T
// double-buffered, k-chunk 16
__device__ __forceinline__ void skinny512(
    const float* __restrict__ W, int ldw,
    float* __restrict__ Cp, int N, int Ksub, int n0, int kyIdx, float* sm)
{
    // layout: [As0(16*68) | Ws0(16*128) | As1(16*68) | Ws1(16*128)]
    int tid  = threadIdx.x;
    int ky   = kyIdx * Ksub;
    int arow = tid >> 3;           // 0..63
    int ak   = (tid & 7) * 2;      // 0..14
    int wrow = tid >> 2;           // 0..127
    int wk   = (tid & 3) * 4;      // 0,4,8,12
    const float* Aload = g_Acat + arow * 1280 + ky + ak;
    const float* Wload = W + (long)(n0 + wrow) * ldw + ky + wk;
    int tb = (tid >> 5) * 4;       // 0..60
    int tc = (tid & 31) * 4;       // 0..124

    float acc[4][4];
#pragma unroll
    for (int i = 0; i < 4; i++)
#pragma unroll
        for (int j = 0; j < 4; j++) acc[i][j] = 0.0f;

    int nch = Ksub >> 4;
    float2 ra = *(const float2*)(Aload);
    float4 rw = *(const float4*)(Wload);
    {
        float* As = sm;
        float* Ws = sm + 16 * 68;
        As[(ak + 0) * 68 + arow] = ra.x;
        As[(ak + 1) * 68 + arow] = ra.y;
        Ws[(wk + 0) * 128 + wrow] = rw.x;
        Ws[(wk + 1) * 128 + wrow] = rw.y;
        Ws[(wk + 2) * 128 + wrow] = rw.z;
        Ws[(wk + 3) * 128 + wrow] = rw.w;
    }
    __syncthreads();

    for (int c = 0; c < nch; c++) {
        if (c + 1 < nch) {
            ra = *(const float2*)(Aload + (c + 1) * 16);
            rw = *(const float4*)(Wload + (c + 1) * 16);
        }
        float* As = sm + (c & 1) * 3136;
        float* Ws = As + 16 * 68;
#pragma unroll
        for (int k = 0; k < 16; k++) {
            float4 av = *(const float4*)&As[k * 68 + tb];
            float4 wv = *(const float4*)&Ws[k * 128 + tc];
            float a[4] = {av.x, av.y, av.z, av.w};
            float w[4] = {wv.x, wv.y, wv.z, wv.w};
#pragma unroll
            for (int i = 0; i < 4; i++)
#pragma unroll
                for (int j = 0; j < 4; j++) acc[i][j] += a[i] * w[j];
        }
        if (c + 1 < nch) {
            float* An = sm + ((c + 1) & 1) * 3136;
            float* Wn = An + 16 * 68;
            An[(ak + 0) * 68 + arow] = ra.x;
            An[(ak + 1) * 68 + arow] = ra.y;
            Wn[(wk + 0) * 128 + wrow] = rw.x;
            Wn[(wk + 1) * 128 + wrow] = rw.y;
            Wn[(wk + 2) * 128 + wrow] = rw.z;
            Wn[(wk + 3) * 128 + wrow] = rw.w;
        }
        __syncthreads();
    }
#pragma unroll
    for (int i = 0; i < 4; i++) {
        float4 v = make_float4(acc[i][0], acc[i][1], acc[i][2], acc[i][3]);
        *(float4*)(Cp + ((long)kyIdx * 64 + tb + i) * N + n0 + tc) = v;
    }
}

// meta cell update + z projections for batch b (one block, 512 threads)
__device__ __forceinline__ void meta_dev(
    int t, int b,
    const float* __restrict__ Wzx_l, const float* __restrict__ Wzh_l,
    const float* __restrict__ Wzb_l,
    const float* __restrict__ bzx_l, const float* __restrict__ bzh_l, float* smem)
{
    float* sm  = smem;          // 1024
    float* smh = smem + 1024;   // 256
    int tid = threadIdx.x;
    const float* mx = g_Mx + ((long)b * 256 + t) * 1024;
#pragma unroll
    for (int jj = 0; jj < 2; jj++) {
        int j = tid + jj * 512;
        float v = mx[j];
#pragma unroll
        for (int ks = 0; ks < 16; ks++) v += g_mpart[(ks * 64 + b) * 1024 + j];
        sm[j] = v;
    }
    __syncthreads();
    if (tid < 256) {
        int j = tid;
        float mi = sm[j], mf = sm[256 + j], mg = sm[512 + j], mo = sm[768 + j];
        float mco = g_mc[b * 256 + j];
        float mc2 = sigf(mf) * mco + sigf(mi) * tanhf(mg);
        float mh2 = sigf(mo) * tanhf(mc2);
        g_mc[b * 256 + j] = mc2;
        g_Acat[b * 1280 + 1024 + j] = mh2;
        smh[j] = mh2;
    }
    __syncthreads();
    if (tid < 128) {
        int g  = tid >> 5;
        int e0 = (tid & 31) * 2;
        float2 ax = *(const float2*)&bzx_l[g * 64 + e0];
        float2 ah = *(const float2*)&bzh_l[g * 64 + e0];
        float2 ab = make_float2(0.0f, 0.0f);
        const float* wx = Wzx_l + g * 64 + e0;   // stride per m: 256
        const float* wh = Wzh_l + g * 64 + e0;
        const float* wb = Wzb_l + g * 64 + e0;
#pragma unroll 4
        for (int m = 0; m < 256; m++) {
            float mv = smh[m];
            float2 vx = *(const float2*)(wx + m * 256);
            float2 vh = *(const float2*)(wh + m * 256);
            float2 vb = *(const float2*)(wb + m * 256);
            ax.x += mv * vx.x; ax.y += mv * vx.y;
            ah.x += mv * vh.x; ah.y += mv * vh.y;
            ab.x += mv * vb.x; ab.y += mv * vb.y;
        }
        int zo = b * 256 + g * 64 + e0;
        *(float2*)&g_z[0 * 64 * 256 + zo] = ax;
        *(float2*)&g_z[1 * 64 * 256 + zo] = ah;
        *(float2*)&g_z[2 * 64 * 256 + zo] = ab;
    }
    __syncthreads();
}

// d[s][b][g*1024+h] = sum_e z[s][b][g,e] * P_s[g][e][h]; 64b x 64hh tile (512-thr block)
__device__ __forceinline__ void dcoef_dev(
    int hhTile, int g, int s,
    const float* __restrict__ Px_l, const float* __restrict__ Ph_l,
    const float* __restrict__ Pb_l, float* smem)
{
    float* zs = smem;             // 64*68
    float* ps = smem + 64 * 68;   // 64*68
    int tid = threadIdx.x;
    int hh0 = hhTile * 64;
    const float* P = (s == 0) ? Px_l : ((s == 1) ? Ph_l : Pb_l);
    {   // z -> zs[e][b]  (512 threads, 8 e each)
        int lb  = tid >> 3;          // 0..63
        int le0 = (tid & 7) * 8;     // 0..56
        const float* zp = g_z + (s * 64 + lb) * 256 + g * 64 + le0;
#pragma unroll
        for (int q = 0; q < 2; q++) {
            float4 v = *(const float4*)(zp + q * 4);
            zs[(le0 + q * 4 + 0) * 68 + lb] = v.x;
            zs[(le0 + q * 4 + 1) * 68 + lb] = v.y;
            zs[(le0 + q * 4 + 2) * 68 + lb] = v.z;
            zs[(le0 + q * 4 + 3) * 68 + lb] = v.w;
        }
    }
    {   // P -> ps[e][hh]
        int le = tid >> 3;           // 0..63
        int j0 = (tid & 7) * 8;      // 0..56
        const float* pp = P + ((long)g * 64 + le) * 1024 + hh0 + j0;
#pragma unroll
        for (int q = 0; q < 2; q++)
            *(float4*)&ps[le * 68 + j0 + q * 4] = *(const float4*)(pp + q * 4);
    }
    __syncthreads();
    if (tid < 256) {
        int tb = (tid >> 4) * 4;
        int th = (tid & 15) * 4;
        float acc[4][4];
#pragma unroll
        for (int i = 0; i < 4; i++)
#pragma unroll
            for (int j = 0; j < 4; j++) acc[i][j] = 0.0f;
#pragma unroll 8
        for (int e = 0; e < 64; e++) {
            float4 zv = *(const float4*)&zs[e * 68 + tb];
            float4 pv = *(const float4*)&ps[e * 68 + th];
            float a[4] = {zv.x, zv.y, zv.z, zv.w};
            float w[4] = {pv.x, pv.y, pv.z, pv.w};
#pragma unroll
            for (int i = 0; i < 4; i++)
#pragma unroll
                for (int j = 0; j < 4; j++) acc[i][j] += a[i] * w[j];
        }
#pragma unroll
        for (int i = 0; i < 4; i++) {
            float4 v = make_float4(acc[i][0], acc[i][1], acc[i][2], acc[i][3]);
            *(float4*)&g_d[((long)s * 64 + tb + i) * 4096 + g * 1024 + hh0 + th] = v;
        }
    }
    __syncthreads();
}

// combine partials, hyper-modulate, LSTM cell update (512 threads per chunk w)
__device__ __forceinline__ void combine_dev(int t, int w, float* __restrict__ Xout)
{
    int idx = w * 512 + threadIdx.x;      // 0..65535 = 64b x 1024h
    int b  = idx >> 10;
    int hh = idx & 1023;
    long rbase = (long)b * 4096 + hh;
    float pre[4];
#pragma unroll
    for (int g = 0; g < 4; g++) {
        long n = rbase + g * 1024;
        float gh = 0.0f;
#pragma unroll
        for (int ks = 0; ks < 8; ks++) gh += g_gpart[(long)ks * 262144 + n];
        float gx = g_Gx[((long)b * 256 + t) * 4096 + g * 1024 + hh];
        pre[g] = g_d[n] * gx + g_d[262144 + n] * gh + g_d[524288 + n];
    }
    float co = g_c[idx];
    float c2 = sigf(pre[1]) * co + sigf(pre[0]) * tanhf(pre[2]);
    float h2 = sigf(pre[3]) * tanhf(c2);
    g_c[idx] = c2;
    g_Acat[b * 1280 + hh] = h2;
    Xout[((long)b * 256 + t) * 1024 + hh] = h2;
}

// ---------------- persistent recurrence: one wave of 148 blocks x 512 threads ----------
__global__ __launch_bounds__(512, 1) void recur_kernel(
    const float* __restrict__ Wh_l,
    const float* __restrict__ Wzx_l, const float* __restrict__ Wzh_l,
    const float* __restrict__ Wzb_l,
    const float* __restrict__ bzx_l, const float* __restrict__ bzh_l,
    const float* __restrict__ Px_l, const float* __restrict__ Ph_l,
    const float* __restrict__ Pb_l,
    float* __restrict__ Xout)
{
    __shared__ __align__(16) float smem[8704];   // 34.8 KB: max of all phase needs
    unsigned nb  = gridDim.x;
    unsigned bid = blockIdx.x;
    int tid = threadIdx.x;
    unsigned sense = g_gen;   // stable across the grid at kernel entry

    // zero state
    for (int i = bid * 512 + tid; i < 64 * 1280; i += nb * 512) g_Acat[i] = 0.0f;
    for (int i = bid * 512 + tid; i < 64 * 1024; i += nb * 512) g_c[i] = 0.0f;
    for (int i = bid * 512 + tid; i < 64 * 256;  i += nb * 512) g_mc[i] = 0.0f;
    gridbar(nb, sense);

    for (int t = 0; t < 256; t++) {
        // Phase A: main h@Wh^T (256 tiles: 32 n x 8 ksplit) + meta GEMM (128 tiles: 8 n x 16 ksplit)
        for (int w = bid; w < 384; w += nb) {
            if (w < 256) {
                skinny512(Wh_l, 1024, g_gpart, 4096, 128, (w & 31) * 128, w >> 5, smem);
            } else {
                int q = w - 256;
                skinny512(g_Wpack, 1280, g_mpart, 1024, 80, (q & 7) * 128, q >> 3, smem);
            }
        }
        gridbar(nb, sense);

        // Phase B: meta cell + z projections (64 batches)
        for (int w = bid; w < 64; w += nb)
            meta_dev(t, w, Wzx_l, Wzh_l, Wzb_l, bzx_l, bzh_l, smem);
        gridbar(nb, sense);

        // Phase C: d = z @ P (192 tiles)
        for (int w = bid; w < 192; w += nb)
            dcoef_dev(w & 15, (w >> 4) & 3, w >> 6, Px_l, Ph_l, Pb_l, smem);
        gridbar(nb, sense);

        // Phase D: combine + LSTM cell update (128 chunks of 512)
        for (int w = bid; w < 128; w += nb)
            combine_dev(t, w, Xout);
        gridbar(nb, sense);
    }
}

// ---------------- host ----------------
extern "C" void kernel_launch(void* const* d_in, const int* in_sizes, int n_in,
                              void* d_out, int out_size)
{
    const float* x   = (const float*)d_in[0];
    const float* Wx  = (const float*)d_in[1];
    const float* Wh  = (const float*)d_in[2];
    const float* Wmx = (const float*)d_in[3];
    const float* Wmh = (const float*)d_in[4];
    const float* bm  = (const float*)d_in[5];
    const float* Wzx = (const float*)d_in[6];
    const float* bzx = (const float*)d_in[7];
    const float* Wzh = (const float*)d_in[8];
    const float* bzh = (const float*)d_in[9];
    const float* Wzb = (const float*)d_in[10];
    const float* Px  = (const float*)d_in[11];
    const float* Ph  = (const float*)d_in[12];
    const float* Pb  = (const float*)d_in[13];

    float *pGx, *pMx, *pX1;
    cudaGetSymbolAddress((void**)&pGx, g_Gx);
    cudaGetSymbolAddress((void**)&pMx, g_Mx);
    cudaGetSymbolAddress((void**)&pX1, g_X1);

    for (int l = 0; l < 2; l++) {
        const float* Xin  = l ? (const float*)pX1 : x;
        float*       Xout = l ? (float*)d_out : pX1;
        const float* Wmx_l = Wmx + (long)l * 1024 * 2048;
        const float* Wmh_l = Wmh + (long)l * 1024 * 256;
        const float* Wh_l  = Wh  + (long)l * 4096 * 1024;
        const float* Wx_l  = Wx  + (long)l * 4096 * 1024;
        const float* Wzx_l = Wzx + (long)l * 65536;
        const float* Wzh_l = Wzh + (long)l * 65536;
        const float* Wzb_l = Wzb + (long)l * 65536;
        const float* bzx_l = bzx + l * 256;
        const float* bzh_l = bzh + l * 256;
        const float* Px_l  = Px + (long)l * 4 * 64 * 1024;
        const float* Ph_l  = Ph + (long)l * 4 * 64 * 1024;
        const float* Pb_l  = Pb + (long)l * 4 * 64 * 1024;

        pack_meta<<<5120, 256>>>(Wmx_l, Wmh_l);
        sgemm128<<<dim3(32, 128), 256>>>(Xin, Wx_l, 1024, nullptr, pGx, 4096);
        sgemm128<<<dim3(8, 128), 256>>>(Xin, Wmx_l, 2048, bm + l * 1024, pMx, 1024);
        recur_kernel<<<148, 512>>>(Wh_l, Wzx_l, Wzh_l, Wzb_l, bzx_l, bzh_l,
                                   Px_l, Ph_l, Pb_l, Xout);
    }
}